// round 9
// baseline (speedup 1.0000x reference)
#include <cuda_runtime.h>
#include <cuda_bf16.h>

#define NBINS 256
#define NCH 3
#define NHIST (NBINS * NCH)       // 768
#define NWORDS (NCH * 128)        // 384 words per column-set (2 bins packed/word)
#define BLOCK_THREADS 256
#define GRID_BLOCKS 591           // 591*256 = 151296 : divisible by 3 and by 32
// stride % 3 == 0  ->  each thread's channel phase is loop-invariant.

// Zero at module load; the fused last-block finalize re-zeroes after reading,
// so every call (correctness run and each graph replay) starts from zero.
__device__ unsigned int g_counts[NHIST];
__device__ unsigned int g_ticket;

__device__ __forceinline__ int bin_of(float x) {
    // TF histogram_fixed_width rule: clip(int(x*256), 0, 255), trunc toward zero
    int b = __float2int_rz(x * 256.0f);
    return max(0, min(255, b));
}

__global__ void __launch_bounds__(BLOCK_THREADS, 4)
hist_kernel(const float4* __restrict__ in4, int n4,
            const float* __restrict__ in, int n_total,
            float* __restrict__ out, float inv_total) {
    // Conflict-FREE packed layout:
    //   word (c, bin>>1, lane) at sh[(c*128 + (bin>>1))*32 + lane]
    //   bin parity selects the 16-bit half: atomicAdd(word, 1 << 16*(bin&1)).
    // Bank = lane for every access -> smem atomic degree 1, always.
    __shared__ unsigned int sh[NWORDS * 32];   // 384*32*4 = 48 KB -> 4 CTAs/SM

    for (int i = threadIdx.x; i < NWORDS * 32; i += BLOCK_THREADS)
        sh[i] = 0u;
    __syncthreads();

    const int lane = threadIdx.x & 31;
    const int stride = GRID_BLOCKS * BLOCK_THREADS;   // % 3 == 0
    int j0 = blockIdx.x * BLOCK_THREADS + threadIdx.x;

    // Channel phase (loop-invariant): float4 j holds channels c0,c0+1,c0+2,c0.
    int c0 = j0 % 3;
    int c1 = c0 + 1; if (c1 == 3) c1 = 0;
    int c2 = c1 + 1; if (c2 == 3) c2 = 0;
    unsigned int* p0 = sh + c0 * (128 * 32) + lane;
    unsigned int* p1 = sh + c1 * (128 * 32) + lane;
    unsigned int* p2 = sh + c2 * (128 * 32) + lane;

    #define ACC(p, xv) do {                                      \
        int _b = bin_of(xv);                                     \
        atomicAdd(&(p)[(_b >> 1) * 32], 1u << ((_b & 1) << 4)); \
    } while (0)

    // Main loop: 4 front-batched loads (MLP_p1 = 4), then 16 packed atomics.
    int j = j0;
    for (; j + 3 * stride < n4; j += 4 * stride) {
        float4 a = in4[j];
        float4 b = in4[j + stride];
        float4 c = in4[j + 2 * stride];
        float4 d = in4[j + 3 * stride];

        ACC(p0, a.x); ACC(p1, a.y); ACC(p2, a.z); ACC(p0, a.w);
        ACC(p0, b.x); ACC(p1, b.y); ACC(p2, b.z); ACC(p0, b.w);
        ACC(p0, c.x); ACC(p1, c.y); ACC(p2, c.z); ACC(p0, c.w);
        ACC(p0, d.x); ACC(p1, d.y); ACC(p2, d.z); ACC(p0, d.w);
    }
    for (; j < n4; j += stride) {
        float4 a = in4[j];
        ACC(p0, a.x); ACC(p1, a.y); ACC(p2, a.z); ACC(p0, a.w);
    }

    // Scalar tail (n_total % 4 != 0) — block 0 only (no-op for this shape)
    if (blockIdx.x == 0) {
        for (int i = n4 * 4 + threadIdx.x; i < n_total; i += BLOCK_THREADS) {
            int c = i % 3;
            int b = bin_of(in[i]);
            atomicAdd(&sh[(c * 128 + (b >> 1)) * 32 + lane],
                      1u << ((b & 1) << 4));
        }
    }

    __syncthreads();

    // Reduce 32 lane-columns per packed word, publish both bins' partials.
    // (col rotation spreads banks across the warp)
    for (int w = threadIdx.x; w < NWORDS; w += BLOCK_THREADS) {
        unsigned int lo = 0u, hi = 0u;
        #pragma unroll
        for (int k = 0; k < 32; k++) {
            unsigned int v = sh[w * 32 + ((k + threadIdx.x) & 31)];
            lo += v & 0xFFFFu;
            hi += v >> 16;
        }
        int c    = w / 128;           // channel
        int bin2 = (w - c * 128) * 2; // even bin of this word
        int base = c * NBINS + bin2;
        if (lo) atomicAdd(&g_counts[base], lo);
        if (hi) atomicAdd(&g_counts[base + 1], hi);
    }

    // Fused finalize: last block to arrive normalizes and resets state.
    __threadfence();
    __shared__ unsigned int ticket;
    if (threadIdx.x == 0) ticket = atomicAdd(&g_ticket, 1u);
    __syncthreads();
    if (ticket == GRID_BLOCKS - 1) {
        for (int i = threadIdx.x; i < NHIST; i += BLOCK_THREADS) {
            unsigned int s = atomicAdd(&g_counts[i], 0u);   // coherent read
            g_counts[i] = 0u;                               // reset for next call
            int c   = i >> 8;
            int bin = i & (NBINS - 1);
            // reference output is hist.T -> [nbins, 3] row-major
            out[bin * NCH + c] = (float)s * inv_total;
        }
        if (threadIdx.x == 0) g_ticket = 0u;                // reset ticket
    }
}

extern "C" void kernel_launch(void* const* d_in, const int* in_sizes, int n_in,
                              void* d_out, int out_size) {
    const float* in = (const float*)d_in[0];
    int n = in_sizes[0];                 // 64*512*512*3 = 50,331,648
    int n4 = n / 4;
    float inv_total = 1.0f / (float)(n / 3);   // per-channel pixel count (exact)

    hist_kernel<<<GRID_BLOCKS, BLOCK_THREADS>>>((const float4*)in, n4, in, n,
                                                (float*)d_out, inv_total);
}

// round 10
// speedup vs baseline: 1.4422x; 1.4422x over previous
#include <cuda_runtime.h>
#include <cuda_bf16.h>

#define NBINS 256
#define NCH 3
#define NHIST (NBINS * NCH)       // 768
#define BLOCK_THREADS 512
#define GRID_BLOCKS 294           // divisible by 3; 2 CTAs/SM fits one wave (296)
// stride = 294*512 = 150528, % 3 == 0 -> channel phase is loop-invariant.

#define SMEM_WORDS (NHIST * 32)   // 24576 words = 96 KB (dynamic)
#define SMEM_BYTES (SMEM_WORDS * 4)

// Zero at module load; the fused last-block finalize re-zeroes after reading,
// so every call (correctness run and each graph replay) starts from zero.
__device__ unsigned int g_counts[NHIST];
__device__ unsigned int g_ticket;

__device__ __forceinline__ int bin_of(float x) {
    // TF histogram_fixed_width rule: clip(int(x*256), 0, 255), trunc toward zero
    int b = __float2int_rz(x * 256.0f);
    return max(0, min(255, b));
}

__global__ void __launch_bounds__(BLOCK_THREADS, 2)
hist_kernel(const float4* __restrict__ in4, int n4,
            const float* __restrict__ in, int n_total,
            float* __restrict__ out, float inv_total) {
    // Fully lane-private layout: counter (c, bin, lane) at
    //   sh[(c*256 + bin)*32 + lane]
    // Bank = lane for EVERY access -> smem atomic conflict degree 1, always,
    // and the address is one LEA (bin<<7 + channel base). No packing ALU.
    extern __shared__ unsigned int sh[];   // 96 KB -> 2 CTAs/SM

    {   // zero with 128-bit stores
        uint4* s4 = (uint4*)sh;
        uint4 z = make_uint4(0u, 0u, 0u, 0u);
        for (int i = threadIdx.x; i < SMEM_WORDS / 4; i += BLOCK_THREADS)
            s4[i] = z;
    }
    __syncthreads();

    const int lane = threadIdx.x & 31;
    const int stride = GRID_BLOCKS * BLOCK_THREADS;   // % 3 == 0
    int j0 = blockIdx.x * BLOCK_THREADS + threadIdx.x;

    // Channel phase (loop-invariant): float4 j holds channels c0,c0+1,c0+2,c0.
    int c0 = j0 % 3;
    int c1 = c0 + 1; if (c1 == 3) c1 = 0;
    int c2 = c1 + 1; if (c2 == 3) c2 = 0;
    unsigned int* p0 = sh + c0 * (NBINS * 32) + lane;
    unsigned int* p1 = sh + c1 * (NBINS * 32) + lane;
    unsigned int* p2 = sh + c2 * (NBINS * 32) + lane;

    #define ACC(p, xv) atomicAdd(&(p)[bin_of(xv) * 32], 1u)

    // Main loop: 4 front-batched loads (MLP_p1 = 4), then 16 shared atomics.
    int j = j0;
    for (; j + 3 * stride < n4; j += 4 * stride) {
        float4 a = in4[j];
        float4 b = in4[j + stride];
        float4 c = in4[j + 2 * stride];
        float4 d = in4[j + 3 * stride];

        ACC(p0, a.x); ACC(p1, a.y); ACC(p2, a.z); ACC(p0, a.w);
        ACC(p0, b.x); ACC(p1, b.y); ACC(p2, b.z); ACC(p0, b.w);
        ACC(p0, c.x); ACC(p1, c.y); ACC(p2, c.z); ACC(p0, c.w);
        ACC(p0, d.x); ACC(p1, d.y); ACC(p2, d.z); ACC(p0, d.w);
    }
    for (; j < n4; j += stride) {
        float4 a = in4[j];
        ACC(p0, a.x); ACC(p1, a.y); ACC(p2, a.z); ACC(p0, a.w);
    }

    // Scalar tail (n_total % 4 != 0) — block 0 only (no-op for this shape)
    if (blockIdx.x == 0) {
        for (int i = n4 * 4 + threadIdx.x; i < n_total; i += BLOCK_THREADS) {
            int c = i % 3;
            atomicAdd(&sh[(c * NBINS + bin_of(in[i])) * 32 + lane], 1u);
        }
    }

    __syncthreads();

    // Reduce the 32 lane-columns per bin (rotated to stay bank-conflict-free),
    // publish block partial to the L2 counters.
    for (int i = threadIdx.x; i < NHIST; i += BLOCK_THREADS) {
        unsigned int s = 0u;
        #pragma unroll
        for (int k = 0; k < 32; k++)
            s += sh[i * 32 + ((k + threadIdx.x) & 31)];
        if (s) atomicAdd(&g_counts[i], s);
    }

    // Fused finalize: last block to arrive normalizes and resets state.
    __threadfence();
    __shared__ unsigned int ticket;
    if (threadIdx.x == 0) ticket = atomicAdd(&g_ticket, 1u);
    __syncthreads();
    if (ticket == GRID_BLOCKS - 1) {
        for (int i = threadIdx.x; i < NHIST; i += BLOCK_THREADS) {
            unsigned int s = atomicAdd(&g_counts[i], 0u);   // coherent read
            g_counts[i] = 0u;                               // reset for next call
            int c   = i >> 8;
            int bin = i & (NBINS - 1);
            // reference output is hist.T -> [nbins, 3] row-major
            out[bin * NCH + c] = (float)s * inv_total;
        }
        if (threadIdx.x == 0) g_ticket = 0u;                // reset ticket
    }
}

extern "C" void kernel_launch(void* const* d_in, const int* in_sizes, int n_in,
                              void* d_out, int out_size) {
    const float* in = (const float*)d_in[0];
    int n = in_sizes[0];                 // 64*512*512*3 = 50,331,648
    int n4 = n / 4;
    float inv_total = 1.0f / (float)(n / 3);   // per-channel pixel count (exact)

    // Raise dynamic-smem limit for the 96 KB table (idempotent, capture-safe).
    cudaFuncSetAttribute(hist_kernel,
                         cudaFuncAttributeMaxDynamicSharedMemorySize, SMEM_BYTES);

    hist_kernel<<<GRID_BLOCKS, BLOCK_THREADS, SMEM_BYTES>>>(
        (const float4*)in, n4, in, n, (float*)d_out, inv_total);
}